// round 8
// baseline (speedup 1.0000x reference)
#include <cuda_runtime.h>
#include <cuda_bf16.h>
#include <math.h>
#include <stdint.h>

#define N_TOT 8192
#define F_DIM 128
#define TBLK  64                 // 8192 / 128
#define NTILES (TBLK*(TBLK+1)/2) // 2080 upper-triangle tiles
#define TILEB 32768              // 128 rows x 256B, XOR-swizzled (no padding)
#define SM_A  0
#define SM_B0 32768
#define SM_B1 65536
#define SM_TOTAL 98304
#define GRID  296                // 2 CTAs per SM

// Device scratch (allocation-free rules)
__device__ __nv_bfloat16 g_xb[N_TOT * F_DIM];   // scaled normalized feats [N][F] bf16
__device__ float g_part[NTILES];

__device__ __forceinline__ uint32_t smem_u32(const void* p) {
    uint32_t a;
    asm("{ .reg .u64 t; cvta.to.shared.u64 t, %1; cvt.u32.u64 %0, t; }" : "=r"(a) : "l"(p));
    return a;
}
__device__ __forceinline__ float ex2a(float x) {
    float y; asm("ex2.approx.f32 %0, %1;" : "=f"(y) : "f"(x)); return y;
}
#define CPA16(dst, src) \
    asm volatile("cp.async.cg.shared.global [%0], [%1], 16;" :: "r"(dst), "l"(src))

// swizzled byte offset of (row r, 16B-chunk q) inside a 128x256B tile
__device__ __forceinline__ uint32_t swz(int r, int q) {
    return (uint32_t)(r * 256 + ((q ^ (r & 7)) << 4));
}

// tile id -> (bi, bj) with bj >= bi; row bi starts at bi*(129-bi)/2
__device__ __forceinline__ void tile_ij(int t, int& bi, int& bj) {
    bi = (int)((129.0f - sqrtf(16641.0f - 8.0f * (float)t)) * 0.5f);
    while ((bi + 1) * (129 - (bi + 1)) / 2 <= t) ++bi;
    while (bi * (129 - bi) / 2 > t) --bi;
    bj = bi + (t - bi * (129 - bi) / 2);
}

// ---------------------------------------------------------------------------
// Kernel 1: normalize + fold sqrt(10/ln2) + bf16 convert. 16 rows per block.
// ---------------------------------------------------------------------------
__global__ void __launch_bounds__(256) normalize_kernel(const float* __restrict__ x) {
    __shared__ float sm[16 * 130];
    __shared__ float ssp[16][17];
    __shared__ float rn[16];

    const int tid = threadIdx.x;
    const int n0  = blockIdx.x * 16;
    const int b   = n0 >> 10;
    const int thw0 = n0 & 1023;
    const float* base = x + (size_t)b * 131072 + thw0;

#pragma unroll
    for (int it = 0; it < 2; ++it) {
        int idx = it * 256 + tid;
        int q = idx & 3;
        int f = idx >> 2;
        float4 v = *(const float4*)&base[(size_t)f * 1024 + q * 4];
        sm[(q * 4 + 0) * 130 + f] = v.x;
        sm[(q * 4 + 1) * 130 + f] = v.y;
        sm[(q * 4 + 2) * 130 + f] = v.z;
        sm[(q * 4 + 3) * 130 + f] = v.w;
    }
    __syncthreads();
    {
        int r = tid & 15, part = tid >> 4;
        float ss = 0.f;
#pragma unroll
        for (int f = part * 8; f < part * 8 + 8; ++f) {
            float v = sm[r * 130 + f];
            ss += v * v;
        }
        ssp[part][r] = ss;
    }
    __syncthreads();
    if (tid < 16) {
        float ss = 0.f;
#pragma unroll
        for (int p = 0; p < 16; ++p) ss += ssp[p][tid];
        // 3.7982825 = sqrt(10 / ln 2): folds the exp2 scale into the data
        rn[tid] = (1.0f / fmaxf(sqrtf(ss), 1e-12f)) * 3.7982825f;
    }
    __syncthreads();
    uint32_t* out = (uint32_t*)(g_xb + (size_t)n0 * F_DIM);
#pragma unroll
    for (int it = 0; it < 4; ++it) {
        int idx = it * 256 + tid;
        int f2 = idx & 63;
        int r  = idx >> 6;
        float s = rn[r];
        float2 v = *(const float2*)&sm[r * 130 + f2 * 2];
        __nv_bfloat162 h = __floats2bfloat162_rn(v.x * s, v.y * s);
        out[r * 64 + f2] = *(uint32_t*)&h;
    }
}

// load one 128x256B operand tile (block row `blk`) into swizzled smem buffer
__device__ __forceinline__ void load_tile(int blk, uint32_t sbuf, int tid) {
    const char* g = (const char*)(g_xb + (size_t)blk * 128 * F_DIM);
#pragma unroll
    for (int it = 0; it < 8; ++it) {
        int idx = it * 256 + tid;
        int r = idx >> 4, q = idx & 15;
        CPA16(sbuf + swz(r, q), g + (size_t)idx * 16);
    }
}

// ---------------------------------------------------------------------------
// Kernel 2: persistent HMMA bf16 tiles; A reused along a row, B double-buffered.
// ---------------------------------------------------------------------------
__global__ void __launch_bounds__(256, 2) simexp_kernel() {
    extern __shared__ char smem[];
    const uint32_t sbase = smem_u32(smem);
    const int tid  = threadIdx.x;
    const int wid  = tid >> 5;
    const int lane = tid & 31;

    const int wm = (wid >> 2) * 64;
    const int wn = (wid & 3) * 32;
    const int g  = lane >> 3;
    const int lr = lane & 7;
    const int lrow = lane >> 2;
    const int lcol = (lane & 3) * 2;

    __shared__ float red[8];

    const int t0 = (int)(((long long)NTILES * blockIdx.x) / GRID);
    const int t1 = (int)(((long long)NTILES * (blockIdx.x + 1)) / GRID);

    int bi, bj;
    tile_ij(t0, bi, bj);

    // prologue: A(bi) and, if off-diag, B(bj)
    load_tile(bi, sbase + SM_A, tid);
    if (bj != bi) load_tile(bj, sbase + SM_B0, tid);
    asm volatile("cp.async.commit_group;");
    asm volatile("cp.async.wait_group 0;" ::: "memory");
    __syncthreads();

    int bcur = 0;
    for (int t = t0; t < t1; ++t) {
        const bool diag = (bi == bj);
        const bool have_next = (t + 1 < t1);
        int nbi = bi, nbj = bj;
        bool same_row = false;
        if (have_next) {
            tile_ij(t + 1, nbi, nbj);
            same_row = (nbi == bi);
            if (same_row) {   // overlap B(t+1) load with compute of t
                load_tile(nbj, sbase + (bcur ? SM_B0 : SM_B1), tid);
                asm volatile("cp.async.commit_group;");
            }
        }

        const uint32_t aBase = sbase + SM_A;
        const uint32_t bBase = diag ? aBase : (sbase + (bcur ? SM_B1 : SM_B0));

        float acc[4][4][4];
#pragma unroll
        for (int mt = 0; mt < 4; ++mt)
#pragma unroll
            for (int nt = 0; nt < 4; ++nt)
#pragma unroll
                for (int c = 0; c < 4; ++c) acc[mt][nt][c] = 0.f;

#pragma unroll
        for (int kc = 0; kc < 8; ++kc) {
            const int qa = kc * 2 + (g >> 1);
            const int qb = kc * 2 + (g & 1);
            uint32_t a[4][4];
#pragma unroll
            for (int mt = 0; mt < 4; ++mt) {
                int row = wm + mt * 16 + (g & 1) * 8 + lr;   // row & 7 == lr
                uint32_t addr = aBase + row * 256 + ((qa ^ lr) << 4);
                asm volatile("ldmatrix.sync.aligned.m8n8.x4.shared.b16 {%0,%1,%2,%3}, [%4];"
                             : "=r"(a[mt][0]), "=r"(a[mt][1]), "=r"(a[mt][2]), "=r"(a[mt][3])
                             : "r"(addr));
            }
            uint32_t bf[2][4];
#pragma unroll
            for (int np = 0; np < 2; ++np) {
                int row = wn + np * 16 + (g >> 1) * 8 + lr;  // row & 7 == lr
                uint32_t addr = bBase + row * 256 + ((qb ^ lr) << 4);
                asm volatile("ldmatrix.sync.aligned.m8n8.x4.shared.b16 {%0,%1,%2,%3}, [%4];"
                             : "=r"(bf[np][0]), "=r"(bf[np][1]), "=r"(bf[np][2]), "=r"(bf[np][3])
                             : "r"(addr));
            }
#pragma unroll
            for (int mt = 0; mt < 4; ++mt)
#pragma unroll
                for (int nt = 0; nt < 4; ++nt) {
                    uint32_t b0 = bf[nt >> 1][(nt & 1) * 2];
                    uint32_t b1 = bf[nt >> 1][(nt & 1) * 2 + 1];
                    asm volatile(
                        "mma.sync.aligned.m16n8k16.row.col.f32.bf16.bf16.f32 "
                        "{%0,%1,%2,%3}, {%4,%5,%6,%7}, {%8,%9}, {%0,%1,%2,%3};"
                        : "+f"(acc[mt][nt][0]), "+f"(acc[mt][nt][1]),
                          "+f"(acc[mt][nt][2]), "+f"(acc[mt][nt][3])
                        : "r"(a[mt][0]), "r"(a[mt][1]), "r"(a[mt][2]), "r"(a[mt][3]),
                          "r"(b0), "r"(b1));
                }
        }

        // epilogue: scale pre-folded -> bare 2^acc; skip i==j on diag tiles
        float s = 0.f;
#pragma unroll
        for (int mt = 0; mt < 4; ++mt)
#pragma unroll
            for (int nt = 0; nt < 4; ++nt)
#pragma unroll
                for (int c = 0; c < 4; ++c) {
                    int r_ = wm + mt * 16 + ((c >> 1) << 3) + lrow;
                    int c_ = wn + nt * 8 + lcol + (c & 1);
                    if (diag && r_ == c_) continue;
                    s += ex2a(acc[mt][nt][c]);
                }
        if (!diag) s *= 2.f;

#pragma unroll
        for (int off = 16; off > 0; off >>= 1)
            s += __shfl_down_sync(0xFFFFFFFFu, s, off);
        if (lane == 0) red[wid] = s;
        __syncthreads();   // also: all warps done reading A/B from smem
        if (tid == 0) {
            float tsum = 0.f;
#pragma unroll
            for (int w = 0; w < 8; ++w) tsum += red[w];
            g_part[t] = tsum;
        }

        if (have_next) {
            if (!same_row) {
                // row change: next tile is the diagonal of row nbi -> A-only load
                load_tile(nbi, sbase + SM_A, tid);
                asm volatile("cp.async.commit_group;");
            }
            asm volatile("cp.async.wait_group 0;" ::: "memory");
            bcur ^= 1;
            bi = nbi; bj = nbj;
        }
        __syncthreads();   // loaded data visible to all; red[] reusable
    }
}

// ---------------------------------------------------------------------------
// Kernel 3: deterministic final reduction + log
// ---------------------------------------------------------------------------
__global__ void __launch_bounds__(256) finalize_kernel(float* __restrict__ out) {
    __shared__ float red[8];
    float s = 0.f;
    for (int i = threadIdx.x; i < NTILES; i += 256) s += g_part[i];
#pragma unroll
    for (int off = 16; off > 0; off >>= 1)
        s += __shfl_down_sync(0xFFFFFFFFu, s, off);
    if ((threadIdx.x & 31) == 0) red[threadIdx.x >> 5] = s;
    __syncthreads();
    if (threadIdx.x == 0) {
        float tsum = 0.f;
#pragma unroll
        for (int w = 0; w < 8; ++w) tsum += red[w];
        out[0] = logf(tsum);
    }
}

extern "C" void kernel_launch(void* const* d_in, const int* in_sizes, int n_in,
                              void* d_out, int out_size) {
    const float* x = (const float*)d_in[0];
    float* out = (float*)d_out;
    (void)in_sizes; (void)n_in; (void)out_size;

    cudaFuncSetAttribute(simexp_kernel, cudaFuncAttributeMaxDynamicSharedMemorySize, SM_TOTAL);

    normalize_kernel<<<N_TOT / 16, 256>>>(x);
    simexp_kernel<<<GRID, 256, SM_TOTAL>>>();
    finalize_kernel<<<1, 256>>>(out);
}